// round 4
// baseline (speedup 1.0000x reference)
#include <cuda_runtime.h>
#include <cuda_bf16.h>
#include <cstdint>

typedef unsigned long long u64;

#define BB 32
#define TT 256
#define II 128
#define HH 128
#define GG 512   // 4*H
#define CC 100
#define WS_PAD 132

// register/smem split for phase 2 recurrent weights
#define RREG 48                 // u64 pairs in registers (k = 0..95)
#define RSM  (64 - RREG)        // u64 pairs in smem     (k = 96..127)

// ---------------- scratch (device globals; no allocation allowed) ----------
__device__ float g_gatesx[TT * BB * GG];      // [t][b][g]
__device__ float g_hist[(TT + 1) * BB * HH];  // [j][b][u], j=1..256 = h_1..h_256
__device__ float g_attn[BB * HH];

__device__ __forceinline__ void fma2(u64 &acc, u64 a, u64 b) {
    asm("fma.rn.f32x2 %0, %1, %2, %0;" : "+l"(acc) : "l"(a), "l"(b));
}
__device__ __forceinline__ float sum2(u64 v) {
    float lo, hi;
    asm("mov.b64 {%0,%1}, %2;" : "=f"(lo), "=f"(hi) : "l"(v));
    return lo + hi;
}
__device__ __forceinline__ float sigacc(float x) {   // accurate sigmoid
    return 0.5f + 0.5f * tanhf(0.5f * x);
}

// ---------------------------------------------------------------------------
// Phase 1: gates_x[t][b][g] = x[b,t,:] . w_ih[g,:] + b_ih[g] + b_hh[g]
// grid (T, 2) blocks x 256 threads. Block = one t, 256 of the 512 gates.
// ---------------------------------------------------------------------------
__global__ void __launch_bounds__(256, 1) phase1_kernel(
    const float* __restrict__ x, const float* __restrict__ w_ih,
    const float* __restrict__ b_ih, const float* __restrict__ b_hh)
{
    extern __shared__ float sm[];
    float* x_s = sm;                 // [32][128]
    float* ws  = sm + BB * II;       // [256][WS_PAD]
    const int t   = blockIdx.x;
    const int gh  = blockIdx.y;
    const int tid = threadIdx.x;

    for (int i = tid; i < BB * II; i += 256) {
        int b = i >> 7, k = i & 127;
        x_s[i] = x[(b * TT + t) * II + k];
    }
    const float* wsrc = w_ih + gh * 256 * II;
    for (int i = tid; i < 256 * II; i += 256) {
        int gl = i >> 7, k = i & 127;
        ws[gl * WS_PAD + k] = wsrc[i];
    }
    if (t == 0 && gh == 0) {   // re-zero attention accumulator every launch
        for (int i = tid; i < BB * HH; i += 256) g_attn[i] = 0.0f;
    }
    __syncthreads();

    const int gl = tid;
    const int g  = gh * 256 + gl;
    const float bias = b_ih[g] + b_hh[g];
    const float* wrow = ws + gl * WS_PAD;

    for (int b0 = 0; b0 < BB; b0 += 8) {
        u64 acc[8];
        #pragma unroll
        for (int j = 0; j < 8; j++) acc[j] = 0ull;
        #pragma unroll
        for (int k0 = 0; k0 < II; k0 += 8) {
            u64 w0 = *(const u64*)(wrow + k0);
            u64 w1v = *(const u64*)(wrow + k0 + 2);
            u64 w2v = *(const u64*)(wrow + k0 + 4);
            u64 w3v = *(const u64*)(wrow + k0 + 6);
            #pragma unroll
            for (int j = 0; j < 8; j++) {
                const float* xr = x_s + (b0 + j) * II + k0;
                fma2(acc[j], w0,  *(const u64*)(xr));
                fma2(acc[j], w1v, *(const u64*)(xr + 2));
                fma2(acc[j], w2v, *(const u64*)(xr + 4));
                fma2(acc[j], w3v, *(const u64*)(xr + 6));
            }
        }
        #pragma unroll
        for (int j = 0; j < 8; j++)
            g_gatesx[(t * BB + b0 + j) * GG + g] = sum2(acc[j]) + bias;
    }
}

// ---------------------------------------------------------------------------
// Phase 2: LSTM recurrence. 32 blocks (one per batch element) x 512 threads
// (one per gate row). Gate order i,f,g,o. Weights: k=0..95 in registers,
// k=96..127 in smem. Writes h_j to g_hist[j], j=1..256.
// ---------------------------------------------------------------------------
__global__ void __launch_bounds__(512, 1) phase2_kernel(const float* __restrict__ w_hh)
{
    extern __shared__ float sm[];
    float* h_s   = sm;                      // [128]
    float* act_s = sm + 128;                // [512]
    u64*   ws2   = (u64*)(sm + 640);        // [RSM/... wait rows][512]
    const int b = blockIdx.x;
    const int g = threadIdx.x;

    const float* wrow = w_hh + g * HH;
    u64 wr[RREG];
    #pragma unroll
    for (int i = 0; i < RREG; i++) wr[i] = *(const u64*)(wrow + 2 * i);
    #pragma unroll
    for (int k2 = 0; k2 < RSM; k2++)
        ws2[k2 * GG + g] = *(const u64*)(wrow + 2 * RREG + 2 * k2);

    float c = 0.0f;
    if (g < HH) h_s[g] = 0.0f;
    __syncthreads();

    const float* gxp = g_gatesx + b * GG + g;
    float gxn = gxp[0];

    for (int t = 0; t < TT; t++) {
        float gxc = gxn;
        if (t + 1 < TT) gxn = gxp[(t + 1) * (BB * GG)];   // prefetch next step

        u64 acc = 0ull;
        #pragma unroll
        for (int i = 0; i < RREG; i++)
            fma2(acc, wr[i], *(const u64*)(h_s + 2 * i));
        #pragma unroll
        for (int k2 = 0; k2 < RSM; k2++)
            fma2(acc, ws2[k2 * GG + g], *(const u64*)(h_s + 2 * RREG + 2 * k2));

        float gate = gxc + sum2(acc);
        // g in [2H,3H) is the cell (g) gate -> tanh; others sigmoid
        float a = (g < 2 * HH || g >= 3 * HH) ? sigacc(gate) : tanhf(gate);
        act_s[g] = a;
        __syncthreads();

        if (g < HH) {
            float sigf = act_s[HH + g];
            float ggv  = act_s[2 * HH + g];
            float sigo = act_s[3 * HH + g];
            c = sigf * c + a * ggv;           // a = sigmoid(i-gate)
            float hv = sigo * tanhf(c);
            h_s[g] = hv;
            g_hist[(t + 1) * (BB * HH) + b * HH + g] = hv;
        }
        __syncthreads();
    }
}

// ---------------------------------------------------------------------------
// Phase 3a: final attention over memory h_1..h_255 (slot 0 and unwritten
// slots are zero and contribute nothing).
//   q[n]   = sum_k h_T[k] * w1[k][n]
//   p_j[n] = sum_k h_j[k] * w1[H+k][n]
//   s_j    = sum_n w2[n] * tanh(q[n] + p_j[n])
//   attn[b][n] += sum_j s_j * h_j[n]
// grid (B, 4) x 256 threads; each block covers 64 j's in 8 tiles of 8.
// ---------------------------------------------------------------------------
__global__ void __launch_bounds__(256, 1) phase3a_kernel(
    const float* __restrict__ w1, const float* __restrict__ w2)
{
    extern __shared__ float sm[];
    float* ws   = sm;                        // [256][WS_PAD]
    float* w2_s = ws + 256 * WS_PAD;         // [128]
    float* hf_s = w2_s + 128;                // [128] = h_T
    float* hj_s = hf_s + 128;                // [8][128]
    float* red  = hj_s + 8 * 128;            // [8][4]
    float* s_t  = red + 32;                  // [8]
    const int b   = blockIdx.x;
    const int jc  = blockIdx.y;
    const int tid = threadIdx.x;
    const int n    = tid & 127;
    const int half = tid >> 7;
    const int lane = tid & 31;
    const int wl   = (tid >> 5) & 3;

    for (int i = tid; i < 2 * HH * HH; i += 256) {
        int k = i >> 7, kk = i & 127;
        ws[k * WS_PAD + kk] = w1[i];
    }
    if (tid < 128) {
        w2_s[tid] = w2[tid];
        hf_s[tid] = g_hist[TT * (BB * HH) + b * HH + tid];
    }
    __syncthreads();

    float q = 0.0f;
    #pragma unroll 4
    for (int k = 0; k < HH; k++) q += hf_s[k] * ws[k * WS_PAD + n];
    const float w2n = w2_s[n];

    float accA = 0.0f;
    const int j0 = 1 + jc * 64;
    const int jb = half * 4;
    const float* wb = ws + HH * WS_PAD + n;

    for (int tile = 0; tile < 8; tile++) {
        int jt = j0 + tile * 8;
        for (int r = 0; r < 4; r++) {
            int lin = r * 256 + tid;
            int jj = lin >> 7, k = lin & 127;
            int j = jt + jj;
            hj_s[jj * 128 + k] = (j <= TT - 1) ? g_hist[j * (BB * HH) + b * HH + k] : 0.0f;
        }
        __syncthreads();

        float p0 = 0, p1 = 0, p2 = 0, p3 = 0;
        #pragma unroll 4
        for (int k = 0; k < HH; k++) {
            float w = wb[k * WS_PAD];
            p0 += hj_s[(jb + 0) * 128 + k] * w;
            p1 += hj_s[(jb + 1) * 128 + k] * w;
            p2 += hj_s[(jb + 2) * 128 + k] * w;
            p3 += hj_s[(jb + 3) * 128 + k] * w;
        }
        float sv[4];
        sv[0] = w2n * tanhf(q + p0);
        sv[1] = w2n * tanhf(q + p1);
        sv[2] = w2n * tanhf(q + p2);
        sv[3] = w2n * tanhf(q + p3);
        #pragma unroll
        for (int jj = 0; jj < 4; jj++) {
            float v = sv[jj];
            v += __shfl_down_sync(0xffffffffu, v, 16);
            v += __shfl_down_sync(0xffffffffu, v, 8);
            v += __shfl_down_sync(0xffffffffu, v, 4);
            v += __shfl_down_sync(0xffffffffu, v, 2);
            v += __shfl_down_sync(0xffffffffu, v, 1);
            if (lane == 0) red[(half * 4 + jj) * 4 + wl] = v;
        }
        __syncthreads();
        if (tid < 8)
            s_t[tid] = red[tid * 4 + 0] + red[tid * 4 + 1] + red[tid * 4 + 2] + red[tid * 4 + 3];
        __syncthreads();

        accA += s_t[jb + 0] * hj_s[(jb + 0) * 128 + n]
              + s_t[jb + 1] * hj_s[(jb + 1) * 128 + n]
              + s_t[jb + 2] * hj_s[(jb + 2) * 128 + n]
              + s_t[jb + 3] * hj_s[(jb + 3) * 128 + n];
        __syncthreads();   // protect hj_s / red / s_t before next tile
    }
    atomicAdd(&g_attn[b * HH + n], accA);
}

// ---------------------------------------------------------------------------
// Phase 3b: out[b] = (h_T + attn[b]) @ w_fc^T + b_fc      (32 x 100 output)
// ---------------------------------------------------------------------------
__global__ void __launch_bounds__(128, 1) phase3b_kernel(
    const float* __restrict__ w_fc, const float* __restrict__ b_fc,
    float* __restrict__ out)
{
    __shared__ float v_s[HH];
    const int b = blockIdx.x, tid = threadIdx.x;
    v_s[tid] = g_hist[TT * (BB * HH) + b * HH + tid] + g_attn[b * HH + tid];
    __syncthreads();
    if (tid < CC) {
        float acc = b_fc[tid];
        const float* wr = w_fc + tid * HH;
        #pragma unroll 4
        for (int k = 0; k < HH; k++) acc += v_s[k] * wr[k];
        out[b * CC + tid] = acc;
    }
}

// ---------------------------------------------------------------------------
extern "C" void kernel_launch(void* const* d_in, const int* in_sizes, int n_in,
                              void* d_out, int out_size)
{
    const float* x    = (const float*)d_in[0];
    const float* w_ih = (const float*)d_in[1];
    const float* b_ih = (const float*)d_in[2];
    const float* w_hh = (const float*)d_in[3];
    const float* b_hh = (const float*)d_in[4];
    const float* w1   = (const float*)d_in[5];
    const float* w2   = (const float*)d_in[6];
    const float* w_fc = (const float*)d_in[7];
    const float* b_fc = (const float*)d_in[8];
    float* out = (float*)d_out;

    const int SM1 = (BB * II + 256 * WS_PAD) * (int)sizeof(float);          // ~151.5 KB
    const int SM2 = 640 * (int)sizeof(float) + RSM * GG * (int)sizeof(u64); // ~68 KB
    const int SM3 = (256 * WS_PAD + 128 + 128 + 8 * 128 + 32 + 8) * (int)sizeof(float);

    cudaFuncSetAttribute(phase1_kernel,  cudaFuncAttributeMaxDynamicSharedMemorySize, SM1);
    cudaFuncSetAttribute(phase2_kernel,  cudaFuncAttributeMaxDynamicSharedMemorySize, SM2);
    cudaFuncSetAttribute(phase3a_kernel, cudaFuncAttributeMaxDynamicSharedMemorySize, SM3);

    phase1_kernel <<<dim3(TT, 2), 256, SM1>>>(x, w_ih, b_ih, b_hh);
    phase2_kernel <<<BB, GG, SM2>>>(w_hh);
    phase3a_kernel<<<dim3(BB, 4), 256, SM3>>>(w1, w2);
    phase3b_kernel<<<BB, HH>>>(w_fc, b_fc, out);
}

// round 5
// speedup vs baseline: 1.2144x; 1.2144x over previous
#include <cuda_runtime.h>
#include <cuda_bf16.h>
#include <cstdint>

typedef unsigned long long u64;

#define BB 32
#define TT 256
#define II 128
#define HH 128
#define GG 512   // 4*H
#define CC 100
#define WS_PAD 132

// phase 2: per gate-row split of the 64 k-pairs
#define RREG 52                 // u64 pairs in registers per row (k = 0..103)
#define RSM  (64 - RREG)        // u64 pairs in smem per row      (k = 104..127)

// ---------------- scratch (device globals; no allocation allowed) ----------
__device__ float g_gatesx[TT * BB * GG];      // [t][b][g]
__device__ float g_hist[(TT + 1) * BB * HH];  // [j][b][u], j=1..256 = h_1..h_256
__device__ float g_attn[BB * HH];

__device__ __forceinline__ void fma2(u64 &acc, u64 a, u64 b) {
    asm("fma.rn.f32x2 %0, %1, %2, %0;" : "+l"(acc) : "l"(a), "l"(b));
}
__device__ __forceinline__ float sum2(u64 v) {
    float lo, hi;
    asm("mov.b64 {%0,%1}, %2;" : "=f"(lo), "=f"(hi) : "l"(v));
    return lo + hi;
}
// fast activations via MUFU ex2 (~1e-7 abs error, fine vs 1e-3 gate)
__device__ __forceinline__ float fast_sig(float x) {
    return __fdividef(1.0f, 1.0f + __expf(-x));
}
__device__ __forceinline__ float fast_tanh(float x) {
    // tanh(x) = 1 - 2/(exp(2x)+1); exp overflow/underflow saturates correctly
    return fmaf(-2.0f, __fdividef(1.0f, __expf(2.0f * x) + 1.0f), 1.0f);
}

// ---------------------------------------------------------------------------
// Phase 1: gates_x[t][b][g] = x[b,t,:] . w_ih[g,:] + b_ih[g] + b_hh[g]
// grid (T, 4) x 256 threads. Block = one t, 128 gates; thread: gate gl=tid&127,
// batch half = tid>>7 (16 batches each). Vectorized LDS.128.
// ---------------------------------------------------------------------------
__global__ void __launch_bounds__(256, 2) phase1_kernel(
    const float* __restrict__ x, const float* __restrict__ w_ih,
    const float* __restrict__ b_ih, const float* __restrict__ b_hh)
{
    extern __shared__ float sm[];
    float* x_s = sm;                 // [32][128]
    float* ws  = sm + BB * II;       // [128][WS_PAD]
    const int t   = blockIdx.x;
    const int gq  = blockIdx.y;      // 0..3: which 128-gate tile
    const int tid = threadIdx.x;

    for (int i = tid; i < BB * II; i += 256) {
        int b = i >> 7, k = i & 127;
        x_s[i] = x[(b * TT + t) * II + k];
    }
    const float* wsrc = w_ih + gq * 128 * II;
    for (int i = tid; i < 128 * II; i += 256) {
        int gl = i >> 7, k = i & 127;
        ws[gl * WS_PAD + k] = wsrc[i];
    }
    if (t == 0 && gq == 0) {   // re-zero attention accumulator every launch
        for (int i = tid; i < BB * HH; i += 256) g_attn[i] = 0.0f;
    }
    __syncthreads();

    const int gl   = tid & 127;
    const int half = tid >> 7;
    const int g    = gq * 128 + gl;
    const float bias = b_ih[g] + b_hh[g];
    const float* wrow = ws + gl * WS_PAD;

    for (int bq = 0; bq < 2; bq++) {
        const int b0 = half * 16 + bq * 8;
        u64 acc[8];
        #pragma unroll
        for (int j = 0; j < 8; j++) acc[j] = 0ull;
        #pragma unroll
        for (int k0 = 0; k0 < II; k0 += 4) {
            ulonglong2 w = *(const ulonglong2*)(wrow + k0);
            #pragma unroll
            for (int j = 0; j < 8; j++) {
                ulonglong2 xv = *(const ulonglong2*)(x_s + (b0 + j) * II + k0);
                fma2(acc[j], w.x, xv.x);
                fma2(acc[j], w.y, xv.y);
            }
        }
        #pragma unroll
        for (int j = 0; j < 8; j++)
            g_gatesx[(t * BB + b0 + j) * GG + g] = sum2(acc[j]) + bias;
    }
}

// ---------------------------------------------------------------------------
// Phase 2: LSTM recurrence. 32 blocks (one per batch) x 256 threads; each
// thread owns TWO gate rows: rowA = tid, rowB = tid + 256.
//   tid<128  : rowA = i-gate(u=tid),     rowB = g-gate(u=tid)
//   tid>=128 : rowA = f-gate(u=tid-128), rowB = o-gate(u=tid-128)
// Weights k=0..103 register-resident per row; k=104..127 from smem.
// ---------------------------------------------------------------------------
__global__ void __launch_bounds__(256, 1) phase2_kernel(const float* __restrict__ w_hh)
{
    extern __shared__ float sm[];
    float* h_s   = sm;                      // [128]  (16B aligned)
    float* act_s = sm + 128;                // [512]: [i|f] 0..255, [g|o] 256..511
    u64*   ws2   = (u64*)(sm + 640);        // [24][256]
    const int b   = blockIdx.x;
    const int tid = threadIdx.x;

    const float* wA = w_hh + tid * HH;
    const float* wB = w_hh + (tid + 256) * HH;
    u64 wrA[RREG], wrB[RREG];
    #pragma unroll
    for (int i = 0; i < RREG; i++) {
        wrA[i] = *(const u64*)(wA + 2 * i);
        wrB[i] = *(const u64*)(wB + 2 * i);
    }
    #pragma unroll
    for (int j = 0; j < RSM; j++) {
        ws2[j * 256 + tid]         = *(const u64*)(wA + 2 * RREG + 2 * j);
        ws2[(RSM + j) * 256 + tid] = *(const u64*)(wB + 2 * RREG + 2 * j);
    }

    float c = 0.0f;
    if (tid < HH) h_s[tid] = 0.0f;
    __syncthreads();

    const float* gxp = g_gatesx + b * GG + tid;
    float gxnA = gxp[0];
    float gxnB = gxp[256];

    const ulonglong2* h2 = (const ulonglong2*)h_s;   // 32 entries of 4 floats

    for (int t = 0; t < TT; t++) {
        float gxA = gxnA, gxB = gxnB;
        if (t + 1 < TT) {
            gxnA = gxp[(t + 1) * (BB * GG)];
            gxnB = gxp[(t + 1) * (BB * GG) + 256];
        }

        u64 accA = 0ull, accB = 0ull;
        #pragma unroll
        for (int i = 0; i < RREG / 2; i++) {         // k = 0 .. 103
            ulonglong2 hv = h2[i];
            fma2(accA, wrA[2 * i],     hv.x);
            fma2(accA, wrA[2 * i + 1], hv.y);
            fma2(accB, wrB[2 * i],     hv.x);
            fma2(accB, wrB[2 * i + 1], hv.y);
        }
        #pragma unroll
        for (int i = 0; i < RSM / 2; i++) {          // k = 104 .. 127
            ulonglong2 hv = h2[RREG / 2 + i];
            fma2(accA, ws2[(2 * i) * 256 + tid],           hv.x);
            fma2(accA, ws2[(2 * i + 1) * 256 + tid],       hv.y);
            fma2(accB, ws2[(RSM + 2 * i) * 256 + tid],     hv.x);
            fma2(accB, ws2[(RSM + 2 * i + 1) * 256 + tid], hv.y);
        }

        float gateA = gxA + sum2(accA);
        float gateB = gxB + sum2(accB);
        float aA = fast_sig(gateA);                          // i or f
        float aB = (tid < 128) ? fast_tanh(gateB)            // g
                               : fast_sig(gateB);            // o
        act_s[tid]       = aA;
        act_s[256 + tid] = aB;
        __syncthreads();

        if (tid < HH) {
            float ai = aA;                    // own i-gate
            float af = act_s[128 + tid];
            float ag = aB;                    // own g-gate
            float ao = act_s[384 + tid];
            c = af * c + ai * ag;
            float hv = ao * fast_tanh(c);
            h_s[tid] = hv;
            g_hist[(t + 1) * (BB * HH) + b * HH + tid] = hv;
        }
        __syncthreads();
    }
}

// ---------------------------------------------------------------------------
// Phase 3a: final attention over memory h_1..h_255.
//   q[n]   = sum_k h_T[k] * w1[k][n]
//   p_j[n] = sum_k h_j[k] * w1[H+k][n]
//   s_j    = sum_n w2[n] * tanh(q[n] + p_j[n])
//   attn[b][n] += sum_j s_j * h_j[n]
// grid (B, 8) x 256 threads; each block covers 32 j's in 4 tiles of 8.
// ---------------------------------------------------------------------------
__global__ void __launch_bounds__(256, 1) phase3a_kernel(
    const float* __restrict__ w1, const float* __restrict__ w2)
{
    extern __shared__ float sm[];
    float* ws   = sm;                        // [256][WS_PAD]
    float* w2_s = ws + 256 * WS_PAD;         // [128]
    float* hf_s = w2_s + 128;                // [128] = h_T
    float* hj_s = hf_s + 128;                // [8][128]
    float* red  = hj_s + 8 * 128;            // [8][4]
    float* s_t  = red + 32;                  // [8]
    const int b   = blockIdx.x;
    const int jc  = blockIdx.y;
    const int tid = threadIdx.x;
    const int n    = tid & 127;
    const int half = tid >> 7;
    const int lane = tid & 31;
    const int wl   = (tid >> 5) & 3;

    for (int i = tid; i < 2 * HH * HH; i += 256) {
        int k = i >> 7, kk = i & 127;
        ws[k * WS_PAD + kk] = w1[i];
    }
    if (tid < 128) {
        w2_s[tid] = w2[tid];
        hf_s[tid] = g_hist[TT * (BB * HH) + b * HH + tid];
    }
    __syncthreads();

    float q = 0.0f;
    #pragma unroll 4
    for (int k = 0; k < HH; k++) q += hf_s[k] * ws[k * WS_PAD + n];
    const float w2n = w2_s[n];

    float accA = 0.0f;
    const int j0 = 1 + jc * 32;
    const int jb = half * 4;
    const float* wb = ws + HH * WS_PAD + n;

    for (int tile = 0; tile < 4; tile++) {
        int jt = j0 + tile * 8;
        for (int r = 0; r < 4; r++) {
            int lin = r * 256 + tid;
            int jj = lin >> 7, k = lin & 127;
            int j = jt + jj;
            hj_s[jj * 128 + k] = (j <= TT - 1) ? g_hist[j * (BB * HH) + b * HH + k] : 0.0f;
        }
        __syncthreads();

        float p0 = 0, p1 = 0, p2 = 0, p3 = 0;
        #pragma unroll 4
        for (int k = 0; k < HH; k++) {
            float w = wb[k * WS_PAD];
            p0 += hj_s[(jb + 0) * 128 + k] * w;
            p1 += hj_s[(jb + 1) * 128 + k] * w;
            p2 += hj_s[(jb + 2) * 128 + k] * w;
            p3 += hj_s[(jb + 3) * 128 + k] * w;
        }
        float sv[4];
        sv[0] = w2n * fast_tanh(q + p0);
        sv[1] = w2n * fast_tanh(q + p1);
        sv[2] = w2n * fast_tanh(q + p2);
        sv[3] = w2n * fast_tanh(q + p3);
        #pragma unroll
        for (int jj = 0; jj < 4; jj++) {
            float v = sv[jj];
            v += __shfl_down_sync(0xffffffffu, v, 16);
            v += __shfl_down_sync(0xffffffffu, v, 8);
            v += __shfl_down_sync(0xffffffffu, v, 4);
            v += __shfl_down_sync(0xffffffffu, v, 2);
            v += __shfl_down_sync(0xffffffffu, v, 1);
            if (lane == 0) red[(half * 4 + jj) * 4 + wl] = v;
        }
        __syncthreads();
        if (tid < 8)
            s_t[tid] = red[tid * 4 + 0] + red[tid * 4 + 1] + red[tid * 4 + 2] + red[tid * 4 + 3];
        __syncthreads();

        accA += s_t[jb + 0] * hj_s[(jb + 0) * 128 + n]
              + s_t[jb + 1] * hj_s[(jb + 1) * 128 + n]
              + s_t[jb + 2] * hj_s[(jb + 2) * 128 + n]
              + s_t[jb + 3] * hj_s[(jb + 3) * 128 + n];
        __syncthreads();   // protect hj_s / red / s_t before next tile
    }
    atomicAdd(&g_attn[b * HH + n], accA);
}

// ---------------------------------------------------------------------------
// Phase 3b: out[b] = (h_T + attn[b]) @ w_fc^T + b_fc      (32 x 100 output)
// float4 weight loads for MLP.
// ---------------------------------------------------------------------------
__global__ void __launch_bounds__(128, 8) phase3b_kernel(
    const float* __restrict__ w_fc, const float* __restrict__ b_fc,
    float* __restrict__ out)
{
    __shared__ float v_s[HH];
    const int b = blockIdx.x, tid = threadIdx.x;
    v_s[tid] = g_hist[TT * (BB * HH) + b * HH + tid] + g_attn[b * HH + tid];
    __syncthreads();
    if (tid < CC) {
        float acc = b_fc[tid];
        const float4* wr4 = (const float4*)(w_fc + tid * HH);
        const float4* v4  = (const float4*)v_s;
        #pragma unroll
        for (int k4 = 0; k4 < HH / 4; k4++) {
            float4 w = wr4[k4];
            float4 v = v4[k4];
            acc += w.x * v.x + w.y * v.y + w.z * v.z + w.w * v.w;
        }
        out[b * CC + tid] = acc;
    }
}

// ---------------------------------------------------------------------------
extern "C" void kernel_launch(void* const* d_in, const int* in_sizes, int n_in,
                              void* d_out, int out_size)
{
    const float* x    = (const float*)d_in[0];
    const float* w_ih = (const float*)d_in[1];
    const float* b_ih = (const float*)d_in[2];
    const float* w_hh = (const float*)d_in[3];
    const float* b_hh = (const float*)d_in[4];
    const float* w1   = (const float*)d_in[5];
    const float* w2   = (const float*)d_in[6];
    const float* w_fc = (const float*)d_in[7];
    const float* b_fc = (const float*)d_in[8];
    float* out = (float*)d_out;

    const int SM1 = (BB * II + 128 * WS_PAD) * (int)sizeof(float);              // ~84 KB
    const int SM2 = 640 * (int)sizeof(float) + 2 * RSM * 256 * (int)sizeof(u64); // ~51.7 KB
    const int SM3 = (256 * WS_PAD + 128 + 128 + 8 * 128 + 32 + 8) * (int)sizeof(float); // ~140.5 KB

    cudaFuncSetAttribute(phase1_kernel,  cudaFuncAttributeMaxDynamicSharedMemorySize, SM1);
    cudaFuncSetAttribute(phase2_kernel,  cudaFuncAttributeMaxDynamicSharedMemorySize, SM2);
    cudaFuncSetAttribute(phase3a_kernel, cudaFuncAttributeMaxDynamicSharedMemorySize, SM3);

    phase1_kernel <<<dim3(TT, 4), 256, SM1>>>(x, w_ih, b_ih, b_hh);
    phase2_kernel <<<BB, 256, SM2>>>(w_hh);
    phase3a_kernel<<<dim3(BB, 8), 256, SM3>>>(w1, w2);
    phase3b_kernel<<<BB, HH>>>(w_fc, b_fc, out);
}